// round 3
// baseline (speedup 1.0000x reference)
#include <cuda_runtime.h>
#include <cstdint>

#define BB 256
#define TT 4096
#define DD 3
#define UU 8

// Packed per-step scan inputs: (0.5*gi, gc, 0.5*go, f) for each (b,t,u).
// 0.5 prescale on i/o so every nonlinearity is tanh: sigmoid(x)=0.5*tanh(0.5x)+0.5
__device__ float4 g_pre[BB * TT * UU];   // 134 MB scratch

// ---------------------------------------------------------------------------
// Kernel 1: fused precompute.
//  (a) signature forget gate: L1 telescopes pointwise; Chen L2 step term is
//      pointwise; L2 = linear 16-channel prefix sum -> block scan; project+sigmoid.
//  (b) x-projection gate pre-activations (+bias, prescaled).
// Emits one float4 per (b,t,u) so the serial scan is load-1-vector-and-go.
// ---------------------------------------------------------------------------
__global__ __launch_bounds__(256) void pre_kernel(const float* __restrict__ x,
                                                  const float* __restrict__ F,
                                                  const float* __restrict__ W,
                                                  const float* __restrict__ bias)
{
    __shared__ float sF[21 * UU];        // forget_kernel (21,8)
    __shared__ float sW[3 * 24];         // input_kernel (3,24)
    __shared__ float sb[32];             // bias
    __shared__ float warp_pre[8][16];

    int b   = blockIdx.x;
    int tid = threadIdx.x;
    if (tid < 21 * UU) sF[tid] = F[tid];
    if (tid < 72)      sW[tid] = W[tid];
    if (tid < 32)      sb[tid] = bias[tid];
    __syncthreads();

    const float* xb = x + (size_t)b * TT * DD;
    const float invTm1 = 1.0f / (float)(TT - 1);
    float p0x = xb[0], p0y = xb[1], p0z = xb[2];

    const int STEPS = 16;
    int k0 = tid * STEPS;

    float C[16];
    #pragma unroll
    for (int i = 0; i < 16; i++) C[i] = 0.f;

    // ---- Phase A: per-thread totals of the 16 L2 channels
    {
        float px = xb[(size_t)k0*3+0], py = xb[(size_t)k0*3+1], pz = xb[(size_t)k0*3+2];
        #pragma unroll 1
        for (int r = 0; r < STEPS; r++) {
            int k = k0 + r;
            if (k < TT - 1) {
                float nx = xb[(size_t)(k+1)*3+0], ny = xb[(size_t)(k+1)*3+1], nz = xb[(size_t)(k+1)*3+2];
                float dx0 = invTm1, dx1 = nx - px, dx2 = ny - py, dx3 = nz - pz;
                float s0 = (float)k * invTm1 + 0.5f * invTm1;
                float s1 = (px - p0x) + 0.5f * dx1;
                float s2 = (py - p0y) + 0.5f * dx2;
                float s3 = (pz - p0z) + 0.5f * dx3;
                C[ 0] += s0*dx0; C[ 1] += s0*dx1; C[ 2] += s0*dx2; C[ 3] += s0*dx3;
                C[ 4] += s1*dx0; C[ 5] += s1*dx1; C[ 6] += s1*dx2; C[ 7] += s1*dx3;
                C[ 8] += s2*dx0; C[ 9] += s2*dx1; C[10] += s2*dx2; C[11] += s2*dx3;
                C[12] += s3*dx0; C[13] += s3*dx1; C[14] += s3*dx2; C[15] += s3*dx3;
                px = nx; py = ny; pz = nz;
            }
        }
    }

    // ---- Block exclusive scan of the 16 channels
    float base[16];
    {
        const unsigned mask = 0xffffffffu;
        int lane = tid & 31, warp = tid >> 5;
        float incl[16];
        #pragma unroll
        for (int c = 0; c < 16; c++) {
            float v = C[c];
            #pragma unroll
            for (int off = 1; off < 32; off <<= 1) {
                float o = __shfl_up_sync(mask, v, off);
                if (lane >= off) v += o;
            }
            incl[c] = v;
        }
        if (lane == 31) {
            #pragma unroll
            for (int c = 0; c < 16; c++) warp_pre[warp][c] = incl[c];
        }
        __syncthreads();
        if (tid == 0) {
            float acc[16];
            #pragma unroll
            for (int c = 0; c < 16; c++) acc[c] = 0.f;
            for (int w = 0; w < 8; w++) {
                #pragma unroll
                for (int c = 0; c < 16; c++) {
                    float tmp = warp_pre[w][c];
                    warp_pre[w][c] = acc[c];
                    acc[c] += tmp;
                }
            }
        }
        __syncthreads();
        #pragma unroll
        for (int c = 0; c < 16; c++)
            base[c] = warp_pre[warp][c] + (incl[c] - C[c]);
    }

    // ---- t = 0 row: sig = (1,0,...,0); gates from x_0
    if (tid == 0) {
        float x0 = xb[0], x1 = xb[1], x2 = xb[2];
        #pragma unroll
        for (int u = 0; u < UU; u++) {
            float f = 1.0f / (1.0f + __expf(-(sF[u] + sb[8 + u])));
            float gi = fmaf(sW[48+u],    x2, fmaf(sW[24+u],    x1, fmaf(sW[u],    x0, sb[u])));
            float gc = fmaf(sW[48+8+u],  x2, fmaf(sW[24+8+u],  x1, fmaf(sW[8+u],  x0, sb[16+u])));
            float go = fmaf(sW[48+16+u], x2, fmaf(sW[24+16+u], x1, fmaf(sW[16+u], x0, sb[24+u])));
            g_pre[(size_t)b * TT * UU + u] = make_float4(0.5f*gi, gc, 0.5f*go, f);
        }
    }

    // ---- Phase B: inclusive rebuild; emit packed (gi, gc, go, f) per (t,u)
    {
        float px = xb[(size_t)k0*3+0], py = xb[(size_t)k0*3+1], pz = xb[(size_t)k0*3+2];
        #pragma unroll 1
        for (int r = 0; r < STEPS; r++) {
            int k = k0 + r;
            if (k < TT - 1) {
                float nx = xb[(size_t)(k+1)*3+0], ny = xb[(size_t)(k+1)*3+1], nz = xb[(size_t)(k+1)*3+2];
                float dx0 = invTm1, dx1 = nx - px, dx2 = ny - py, dx3 = nz - pz;
                float s0 = (float)k * invTm1 + 0.5f * invTm1;
                float s1 = (px - p0x) + 0.5f * dx1;
                float s2 = (py - p0y) + 0.5f * dx2;
                float s3 = (pz - p0z) + 0.5f * dx3;
                base[ 0] += s0*dx0; base[ 1] += s0*dx1; base[ 2] += s0*dx2; base[ 3] += s0*dx3;
                base[ 4] += s1*dx0; base[ 5] += s1*dx1; base[ 6] += s1*dx2; base[ 7] += s1*dx3;
                base[ 8] += s2*dx0; base[ 9] += s2*dx1; base[10] += s2*dx2; base[11] += s2*dx3;
                base[12] += s3*dx0; base[13] += s3*dx1; base[14] += s3*dx2; base[15] += s3*dx3;
                px = nx; py = ny; pz = nz;

                int t = k + 1;
                float tg    = (float)t * invTm1;
                float invtg = (float)(TT - 1) / (float)t;
                float dX = px - p0x, dY = py - p0y, dZ = pz - p0z;  // L1 at t
                size_t outb = (size_t)b * TT * UU + (size_t)t * UU;
                #pragma unroll
                for (int u = 0; u < UU; u++) {
                    float acc = sF[u] + tg * sF[8+u] + dX * sF[16+u] + dY * sF[24+u] + dZ * sF[32+u];
                    #pragma unroll
                    for (int ab = 0; ab < 16; ab++)
                        acc += base[ab] * sF[(5 + ab) * 8 + u];
                    float f = 1.0f / (1.0f + __expf(-(acc * invtg + sb[8 + u])));
                    // x-projection (x_t = px,py,pz after update)
                    float gi = fmaf(sW[48+u],    pz, fmaf(sW[24+u],    py, fmaf(sW[u],    px, sb[u])));
                    float gc = fmaf(sW[48+8+u],  pz, fmaf(sW[24+8+u],  py, fmaf(sW[8+u],  px, sb[16+u])));
                    float go = fmaf(sW[48+16+u], pz, fmaf(sW[24+16+u], py, fmaf(sW[16+u], px, sb[24+u])));
                    g_pre[outb + u] = make_float4(0.5f*gi, gc, 0.5f*go, f);
                }
            }
        }
    }
}

// ---------------------------------------------------------------------------
// Kernel 2: the serial scan. 4 batches/warp, lane owns (batch, unit).
// Body per step: 8 SHFL + 27 FMA (dots) + 4 tanh.approx + 5 update ops + STG,
// with float4 gate vectors prefetched 8 steps ahead.
// ---------------------------------------------------------------------------
__device__ __forceinline__ float ftanh(float v)
{
    float y;
    asm("tanh.approx.f32 %0, %1;" : "=f"(y) : "f"(v));
    return y;
}

#define UNROLL_G 8

__global__ __launch_bounds__(32, 1) void scan_kernel(const float* __restrict__ rk,
                                                     float* __restrict__ out)
{
    const unsigned FULL = 0xffffffffu;
    int lane = threadIdx.x;
    int grp  = lane >> 3;
    int u    = lane & 7;
    int b    = blockIdx.x * 4 + grp;

    float Ri[8], Rc[8], Ro[8];
    #pragma unroll
    for (int k = 0; k < 8; k++) {
        Ri[k] = 0.5f * __ldg(rk + k*24 + u);
        Rc[k] =        __ldg(rk + k*24 + 8 + u);
        Ro[k] = 0.5f * __ldg(rk + k*24 + 16 + u);
    }

    const float4* pb = g_pre + (size_t)b * TT * UU;
    float*        ob = out   + (size_t)b * TT * UU;

    float h = 0.f, c = 0.f;

    float4 cur[UNROLL_G], nxt[UNROLL_G];
    #pragma unroll
    for (int j = 0; j < UNROLL_G; j++)
        cur[j] = __ldg(&pb[(size_t)j * 8 + u]);

    const int NG = TT / UNROLL_G;
    for (int g = 0; g < NG; g++) {
        int gn = (g + 1 < NG) ? (g + 1) : g;
        #pragma unroll
        for (int j = 0; j < UNROLL_G; j++)
            nxt[j] = __ldg(&pb[(size_t)(gn * UNROLL_G + j) * 8 + u]);

        #pragma unroll
        for (int j = 0; j < UNROLL_G; j++) {
            float h0 = __shfl_sync(FULL, h, 0, 8);
            float h1 = __shfl_sync(FULL, h, 1, 8);
            float h2 = __shfl_sync(FULL, h, 2, 8);
            float h3 = __shfl_sync(FULL, h, 3, 8);
            float h4 = __shfl_sync(FULL, h, 4, 8);
            float h5 = __shfl_sync(FULL, h, 5, 8);
            float h6 = __shfl_sync(FULL, h, 6, 8);
            float h7 = __shfl_sync(FULL, h, 7, 8);

            float ai0 = fmaf(Ri[0],h0, cur[j].x); ai0 = fmaf(Ri[1],h1, ai0);
            ai0 = fmaf(Ri[2],h2, ai0);            ai0 = fmaf(Ri[3],h3, ai0);
            float ai1 = Ri[4]*h4;                 ai1 = fmaf(Ri[5],h5, ai1);
            ai1 = fmaf(Ri[6],h6, ai1);            ai1 = fmaf(Ri[7],h7, ai1);

            float ac0 = fmaf(Rc[0],h0, cur[j].y); ac0 = fmaf(Rc[1],h1, ac0);
            ac0 = fmaf(Rc[2],h2, ac0);            ac0 = fmaf(Rc[3],h3, ac0);
            float ac1 = Rc[4]*h4;                 ac1 = fmaf(Rc[5],h5, ac1);
            ac1 = fmaf(Rc[6],h6, ac1);            ac1 = fmaf(Rc[7],h7, ac1);

            float ao0 = fmaf(Ro[0],h0, cur[j].z); ao0 = fmaf(Ro[1],h1, ao0);
            ao0 = fmaf(Ro[2],h2, ao0);            ao0 = fmaf(Ro[3],h3, ao0);
            float ao1 = Ro[4]*h4;                 ao1 = fmaf(Ro[5],h5, ao1);
            ao1 = fmaf(Ro[6],h6, ao1);            ao1 = fmaf(Ro[7],h7, ao1);

            float ti  = ftanh(ai0 + ai1);   // sigmoid(i) = 0.5*ti+0.5
            float tch = ftanh(ac0 + ac1);   // tanh(c_hat)
            float to  = ftanh(ao0 + ao1);   // sigmoid(o) = 0.5*to+0.5

            float q = 0.5f * tch;
            c = fmaf(cur[j].w, c, fmaf(ti, q, q));   // f*c + i*chat
            float tc = ftanh(c);
            float r = 0.5f * tc;
            h = fmaf(to, r, r);                      // o * tanh(c)

            ob[(size_t)(g * UNROLL_G + j) * 8 + u] = h;
        }

        #pragma unroll
        for (int j = 0; j < UNROLL_G; j++) cur[j] = nxt[j];
    }
}

// ---------------------------------------------------------------------------
extern "C" void kernel_launch(void* const* d_in, const int* in_sizes, int n_in,
                              void* d_out, int out_size)
{
    const float* x  = (const float*)d_in[0];   // inputs (B,T,3)
    const float* Wi = (const float*)d_in[1];   // input_kernel (3,24)
    const float* Rk = (const float*)d_in[2];   // recurrent_kernel (8,24)
    const float* Fk = (const float*)d_in[3];   // forget_kernel (21,8)
    const float* bs = (const float*)d_in[4];   // bias (32,)
    float* out = (float*)d_out;

    pre_kernel<<<BB, 256>>>(x, Fk, Wi, bs);
    scan_kernel<<<BB/4, 32>>>(Rk, out);
}